// round 1
// baseline (speedup 1.0000x reference)
#include <cuda_runtime.h>
#include <math.h>

#define BATCH  2
#define SEQ    2048
#define DMODEL 1024
#define NHEAD  16
#define HDIM   64
#define WIN    256
#define MROWS  (BATCH*SEQ)   /* 4096 */

// ---------------- scratch (allocation-free rule: device globals) ----------------
__device__ float g_q [MROWS*DMODEL];
__device__ float g_k [MROWS*DMODEL];
__device__ float g_v [MROWS*DMODEL];
__device__ float g_ao[MROWS*DMODEL];

// ---------------------------------------------------------------------------
// C[M,N] = A[M,K] * W[N,K]^T      (A row-major MxK, W row-major NxK)
// 128x128 block tile, BK=16, 256 threads, 8x8 per-thread microtile.
// M,N multiples of 128, K multiple of 16 (true for all 4 calls) -> no guards.
// ---------------------------------------------------------------------------
template<int M, int N, int K>
__global__ __launch_bounds__(256)
void gemm_nt(const float* __restrict__ A, const float* __restrict__ W,
             float* __restrict__ C)
{
    constexpr int BM = 128, BN = 128, BK = 16;
    __shared__ __align__(16) float As[BK][BM + 4];
    __shared__ __align__(16) float Bs[BK][BN + 4];

    const int tid = threadIdx.x;
    const int bx = blockIdx.x;   // N tile
    const int by = blockIdx.y;   // M tile

    const float* Ablk = A + (size_t)by * BM * K;
    const float* Wblk = W + (size_t)bx * BN * K;

    const int ty = tid >> 4;     // 0..15  -> 8 rows each
    const int tx = tid & 15;     // 0..15  -> 8 cols each

    float c[8][8] = {};

    for (int kt = 0; kt < K; kt += BK) {
        // load 128x16 of A and W, transposed into smem
        #pragma unroll
        for (int p = 0; p < 2; p++) {
            int idx = tid + p * 256;          // 0..511
            int row = idx >> 2;               // 0..127
            int k4  = (idx & 3) * 4;          // 0,4,8,12
            float4 a = *(const float4*)(Ablk + (size_t)row * K + kt + k4);
            float4 b = *(const float4*)(Wblk + (size_t)row * K + kt + k4);
            As[k4+0][row] = a.x; As[k4+1][row] = a.y;
            As[k4+2][row] = a.z; As[k4+3][row] = a.w;
            Bs[k4+0][row] = b.x; Bs[k4+1][row] = b.y;
            Bs[k4+2][row] = b.z; Bs[k4+3][row] = b.w;
        }
        __syncthreads();

        #pragma unroll
        for (int kk = 0; kk < BK; kk++) {
            float4 a0 = *(const float4*)&As[kk][ty*8];
            float4 a1 = *(const float4*)&As[kk][ty*8 + 4];
            float4 b0 = *(const float4*)&Bs[kk][tx*8];
            float4 b1 = *(const float4*)&Bs[kk][tx*8 + 4];
            float av[8] = {a0.x,a0.y,a0.z,a0.w,a1.x,a1.y,a1.z,a1.w};
            float bv[8] = {b0.x,b0.y,b0.z,b0.w,b1.x,b1.y,b1.z,b1.w};
            #pragma unroll
            for (int i = 0; i < 8; i++)
                #pragma unroll
                for (int j = 0; j < 8; j++)
                    c[i][j] += av[i] * bv[j];
        }
        __syncthreads();
    }

    float* Cblk = C + (size_t)(by * BM) * N + bx * BN;
    #pragma unroll
    for (int i = 0; i < 8; i++) {
        float* crow = Cblk + (size_t)(ty*8 + i) * N + tx*8;
        *(float4*)(crow)     = make_float4(c[i][0], c[i][1], c[i][2], c[i][3]);
        *(float4*)(crow + 4) = make_float4(c[i][4], c[i][5], c[i][6], c[i][7]);
    }
}

// ---------------------------------------------------------------------------
// Sliding-window attention, fp32, online softmax.
// grid = (SEQ/32, NHEAD, BATCH), 128 threads.
// Each block: 32 query rows for one (b,h). 4 threads per row (sub = tid&3),
// each owning 16 of 64 keys per key tile; per-thread partial (l, o[64])
// reduced across the group of 4 at the end via shfl.
// ---------------------------------------------------------------------------
__global__ __launch_bounds__(128)
void attn_kernel(const float* __restrict__ q, const float* __restrict__ k,
                 const float* __restrict__ v, float* __restrict__ o)
{
    constexpr int BQ = 32;
    __shared__ __align__(16) float Qs[BQ][HDIM];
    __shared__ __align__(16) float Ks[64][HDIM + 4];
    __shared__ __align__(16) float Vs[64][HDIM + 4];

    const int b  = blockIdx.z;
    const int h  = blockIdx.y;
    const int q0 = blockIdx.x * BQ;
    const int tid = threadIdx.x;
    const int r   = tid >> 2;     // query row in tile (0..31)
    const int sub = tid & 3;      // key-subset owner (0..3)

    const float* qb = q + (size_t)b * SEQ * DMODEL + h * HDIM;
    const float* kp = k + (size_t)b * SEQ * DMODEL + h * HDIM;
    const float* vp = v + (size_t)b * SEQ * DMODEL + h * HDIM;

    const float scale = 0.125f;   // 1/sqrt(64)

    // load + scale Q tile (32x64)
    for (int i = tid; i < BQ * (HDIM/4); i += 128) {
        int row = i >> 4;
        int c4  = (i & 15) * 4;
        float4 t = *(const float4*)(qb + (size_t)(q0 + row) * DMODEL + c4);
        t.x *= scale; t.y *= scale; t.z *= scale; t.w *= scale;
        *(float4*)&Qs[row][c4] = t;
    }
    __syncthreads();

    float4 qr[16];
    #pragma unroll
    for (int i = 0; i < 16; i++) qr[i] = *(const float4*)&Qs[r][i*4];

    const int qidx = q0 + r;
    float m = -INFINITY, l = 0.f;
    float4 oa[16];
    #pragma unroll
    for (int i = 0; i < 16; i++) oa[i] = make_float4(0.f, 0.f, 0.f, 0.f);

    int kstart = max(0, q0 - WIN + 1) & ~63;

    for (int kb = kstart; kb <= q0 + BQ - 1; kb += 64) {
        __syncthreads();   // protect previous tile's smem
        for (int i = tid; i < 64 * 16; i += 128) {
            int row = i >> 4;
            int c4  = (i & 15) * 4;
            *(float4*)&Ks[row][c4] = *(const float4*)(kp + (size_t)(kb + row) * DMODEL + c4);
            *(float4*)&Vs[row][c4] = *(const float4*)(vp + (size_t)(kb + row) * DMODEL + c4);
        }
        __syncthreads();

        float sc[16];
        float tmax = -INFINITY;
        #pragma unroll
        for (int i = 0; i < 16; i++) {
            int kk = sub + 4 * i;
            int kg = kb + kk;
            float s = -INFINITY;
            if (kg <= qidx && kg >= qidx - WIN + 1) {
                float acc = 0.f;
                #pragma unroll
                for (int d4 = 0; d4 < 16; d4++) {
                    float4 kv = *(const float4*)&Ks[kk][d4*4];
                    acc += qr[d4].x*kv.x + qr[d4].y*kv.y
                         + qr[d4].z*kv.z + qr[d4].w*kv.w;
                }
                s = acc;
            }
            sc[i] = s;
            tmax = fmaxf(tmax, s);
        }
        tmax = fmaxf(tmax, __shfl_xor_sync(0xffffffffu, tmax, 1));
        tmax = fmaxf(tmax, __shfl_xor_sync(0xffffffffu, tmax, 2));

        float mnew = fmaxf(m, tmax);
        // m == -inf -> nothing accumulated yet -> factor 0 keeps state clean,
        // also guards the fully-masked-first-tile case (mnew == -inf).
        float factor = (m == -INFINITY) ? 0.f : __expf(m - mnew);
        l *= factor;
        #pragma unroll
        for (int i = 0; i < 16; i++) {
            oa[i].x *= factor; oa[i].y *= factor;
            oa[i].z *= factor; oa[i].w *= factor;
        }
        #pragma unroll
        for (int i = 0; i < 16; i++) {
            float s = sc[i];
            if (s == -INFINITY) continue;
            float p = __expf(s - mnew);
            l += p;
            int kk = sub + 4 * i;
            #pragma unroll
            for (int d4 = 0; d4 < 16; d4++) {
                float4 vv = *(const float4*)&Vs[kk][d4*4];
                oa[d4].x += p * vv.x; oa[d4].y += p * vv.y;
                oa[d4].z += p * vv.z; oa[d4].w += p * vv.w;
            }
        }
        m = mnew;
    }

    // reduce (l, o) across the group of 4 lanes
    l += __shfl_xor_sync(0xffffffffu, l, 1);
    l += __shfl_xor_sync(0xffffffffu, l, 2);
    #pragma unroll
    for (int i = 0; i < 16; i++) {
        oa[i].x += __shfl_xor_sync(0xffffffffu, oa[i].x, 1);
        oa[i].x += __shfl_xor_sync(0xffffffffu, oa[i].x, 2);
        oa[i].y += __shfl_xor_sync(0xffffffffu, oa[i].y, 1);
        oa[i].y += __shfl_xor_sync(0xffffffffu, oa[i].y, 2);
        oa[i].z += __shfl_xor_sync(0xffffffffu, oa[i].z, 1);
        oa[i].z += __shfl_xor_sync(0xffffffffu, oa[i].z, 2);
        oa[i].w += __shfl_xor_sync(0xffffffffu, oa[i].w, 1);
        oa[i].w += __shfl_xor_sync(0xffffffffu, oa[i].w, 2);
    }

    float inv = 1.f / l;   // window always contains key==query -> l > 0
    float* ob = o + (size_t)(b * SEQ + qidx) * DMODEL + h * HDIM + sub * 16;
    #pragma unroll
    for (int t = 0; t < 4; t++) {
        float4 val = oa[sub * 4 + t];
        val.x *= inv; val.y *= inv; val.z *= inv; val.w *= inv;
        *(float4*)(ob + t * 4) = val;
    }
}

// ---------------------------------------------------------------------------
extern "C" void kernel_launch(void* const* d_in, const int* in_sizes, int n_in,
                              void* d_out, int out_size)
{
    const float* x  = (const float*)d_in[0];
    const float* Wq = (const float*)d_in[1];
    const float* Wk = (const float*)d_in[2];
    const float* Wv = (const float*)d_in[3];
    const float* Wo = (const float*)d_in[4];
    float* out = (float*)d_out;

    float *qp, *kp, *vp, *aop;
    cudaGetSymbolAddress((void**)&qp,  g_q);
    cudaGetSymbolAddress((void**)&kp,  g_k);
    cudaGetSymbolAddress((void**)&vp,  g_v);
    cudaGetSymbolAddress((void**)&aop, g_ao);

    dim3 gdim(DMODEL / 128, MROWS / 128);  // (8, 32)

    gemm_nt<MROWS, DMODEL, DMODEL><<<gdim, 256>>>(x, Wq, qp);
    gemm_nt<MROWS, DMODEL, DMODEL><<<gdim, 256>>>(x, Wk, kp);
    gemm_nt<MROWS, DMODEL, DMODEL><<<gdim, 256>>>(x, Wv, vp);

    attn_kernel<<<dim3(SEQ / 32, NHEAD, BATCH), 128>>>(qp, kp, vp, aop);

    gemm_nt<MROWS, DMODEL, DMODEL><<<gdim, 256>>>(aop, Wo, out);
}

// round 4
// speedup vs baseline: 2.2723x; 2.2723x over previous
#include <cuda_runtime.h>
#include <cuda_bf16.h>
#include <cstdint>
#include <math.h>

#define BATCH  2
#define SEQ    2048
#define DMODEL 1024
#define NHEAD  16
#define HDIM   64
#define WIN    256
#define MROWS  (BATCH*SEQ)   /* 4096 */

#define KC     3072          /* [hi|hi|lo] x [hi|lo|hi] concatenated K */
#define GN     1024

// ---------------- scratch (allocation-free rule: device globals) ----------------
__device__ float g_q [MROWS*DMODEL];
__device__ float g_k [MROWS*DMODEL];
__device__ float g_v [MROWS*DMODEL];
__device__ float g_ao[MROWS*DMODEL];

__device__ __nv_bfloat16 g_xc [(size_t)MROWS*KC];   // x split  (A-side: hi|hi|lo)
__device__ __nv_bfloat16 g_aoc[(size_t)MROWS*KC];   // attn-out (A-side: hi|hi|lo)
__device__ __nv_bfloat16 g_wqc[(size_t)DMODEL*KC];  // weights  (B-side: hi|lo|hi)
__device__ __nv_bfloat16 g_wkc[(size_t)DMODEL*KC];
__device__ __nv_bfloat16 g_wvc[(size_t)DMODEL*KC];
__device__ __nv_bfloat16 g_woc[(size_t)DMODEL*KC];

// =========================================================================
// fp32 [rows x 1024] -> bf16 [rows x 3072] splits.
// conv_A: segments [hi | hi | lo];  conv_B: segments [hi | lo | hi].
// grid = rows, 256 threads, one float4 per thread.
// =========================================================================
__device__ __forceinline__ void split4(float4 v, uint2& hi, uint2& lo)
{
    __nv_bfloat162 h01 = __floats2bfloat162_rn(v.x, v.y);
    __nv_bfloat162 h23 = __floats2bfloat162_rn(v.z, v.w);
    __nv_bfloat162 l01 = __floats2bfloat162_rn(v.x - __low2float(h01),
                                               v.y - __high2float(h01));
    __nv_bfloat162 l23 = __floats2bfloat162_rn(v.z - __low2float(h23),
                                               v.w - __high2float(h23));
    hi = make_uint2(*(uint32_t*)&h01, *(uint32_t*)&h23);
    lo = make_uint2(*(uint32_t*)&l01, *(uint32_t*)&l23);
}

__global__ __launch_bounds__(256)
void conv_A(const float* __restrict__ in, __nv_bfloat16* __restrict__ out)
{
    size_t idx = (size_t)blockIdx.x * 256 + threadIdx.x;
    int r  = (int)(idx >> 8);
    int c4 = (int)(idx & 255);
    uint2 hi, lo;
    split4(((const float4*)in)[idx], hi, lo);
    __nv_bfloat16* row = out + (size_t)r * KC;
    *(uint2*)(row + c4 * 4)        = hi;
    *(uint2*)(row + 1024 + c4 * 4) = hi;
    *(uint2*)(row + 2048 + c4 * 4) = lo;
}

__global__ __launch_bounds__(256)
void conv_B(const float* __restrict__ in, __nv_bfloat16* __restrict__ out)
{
    size_t idx = (size_t)blockIdx.x * 256 + threadIdx.x;
    int r  = (int)(idx >> 8);
    int c4 = (int)(idx & 255);
    uint2 hi, lo;
    split4(((const float4*)in)[idx], hi, lo);
    __nv_bfloat16* row = out + (size_t)r * KC;
    *(uint2*)(row + c4 * 4)        = hi;
    *(uint2*)(row + 1024 + c4 * 4) = lo;
    *(uint2*)(row + 2048 + c4 * 4) = hi;
}

// =========================================================================
// C[M,1024] = A[M,3072] * B[1024,3072]^T  (bf16 in, fp32 out) via mma.sync
// 128x128 CTA tile, BK=32, 3-stage cp.async, 8 warps of 64x32.
// =========================================================================
#define BKT    32
#define NSTG   3
#define NKT    (KC / BKT)            /* 96 */
#define LDK    40                    /* smem row stride in bf16 (pad for ldmatrix) */
#define TILE_SB (128 * LDK * 2)      /* 10240 B per operand tile */
#define STAGE_B (2 * TILE_SB)        /* 20480 */
#define SMEM_GEMM (NSTG * STAGE_B)   /* 61440 */

__device__ __forceinline__ uint32_t smem_u32(const void* p) {
    uint32_t a;
    asm("{ .reg .u64 t; cvta.to.shared.u64 t, %1; cvt.u32.u64 %0, t; }"
        : "=r"(a) : "l"(p));
    return a;
}

#define CP_ASYNC16(dst, src) \
    asm volatile("cp.async.cg.shared.global [%0], [%1], 16;" \
                 :: "r"(dst), "l"(src) : "memory")
#define CP_COMMIT() asm volatile("cp.async.commit_group;" ::: "memory")
#define CP_WAIT1()  asm volatile("cp.async.wait_group 1;"  ::: "memory")

#define LDMATRIX_X4(r0, r1, r2, r3, addr) \
    asm volatile("ldmatrix.sync.aligned.m8n8.x4.shared.b16 {%0,%1,%2,%3}, [%4];" \
                 : "=r"(r0), "=r"(r1), "=r"(r2), "=r"(r3) : "r"(addr))

#define MMA16816(d, a, b) \
    asm volatile("mma.sync.aligned.m16n8k16.row.col.f32.bf16.bf16.f32 " \
                 "{%0,%1,%2,%3}, {%4,%5,%6,%7}, {%8,%9}, {%0,%1,%2,%3};" \
                 : "+f"((d)[0]), "+f"((d)[1]), "+f"((d)[2]), "+f"((d)[3]) \
                 : "r"((a)[0]), "r"((a)[1]), "r"((a)[2]), "r"((a)[3]), \
                   "r"((b)[0]), "r"((b)[1]))

__global__ __launch_bounds__(256)
void gemm_mma(const __nv_bfloat16* __restrict__ A,
              const __nv_bfloat16* __restrict__ B,
              float* __restrict__ C)
{
    extern __shared__ __align__(128) char smem[];
    const uint32_t sb = smem_u32(smem);

    const int tid  = threadIdx.x;
    const int lane = tid & 31;
    const int wid  = tid >> 5;
    const int wm   = (wid & 1) * 64;    // warp row offset in tile
    const int wn   = (wid >> 1) * 32;   // warp col offset in tile

    const __nv_bfloat16* Ag = A + (size_t)(blockIdx.y * 128) * KC;
    const __nv_bfloat16* Bg = B + (size_t)(blockIdx.x * 128) * KC;

    const int cr = tid >> 2;     // row 0..63 (+64 on second iter)
    const int cc = tid & 3;      // 16B chunk in row (8 bf16)

    const int arow  = ((lane >> 3) & 1) * 8 + (lane & 7);
    const int ahalf = (lane >> 4) * 8;
    const int brow  = ((lane >> 4) << 3) + (lane & 7);
    const int bhalf = ((lane >> 3) & 1) * 8;

    float acc[4][4][4];
    #pragma unroll
    for (int i = 0; i < 4; i++)
        #pragma unroll
        for (int j = 0; j < 4; j++)
            #pragma unroll
            for (int t = 0; t < 4; t++) acc[i][j][t] = 0.f;

    // ---- prologue: issue stages 0..NSTG-2 ----
    #pragma unroll
    for (int s = 0; s < NSTG - 1; s++) {
        uint32_t sa = sb + s * STAGE_B;
        #pragma unroll
        for (int i = 0; i < 2; i++) {
            int r = cr + i * 64;
            CP_ASYNC16(sa + (uint32_t)((r * LDK + cc * 8) * 2),
                       Ag + (size_t)r * KC + s * BKT + cc * 8);
            CP_ASYNC16(sa + TILE_SB + (uint32_t)((r * LDK + cc * 8) * 2),
                       Bg + (size_t)r * KC + s * BKT + cc * 8);
        }
        CP_COMMIT();
    }

    for (int kt = 0; kt < NKT; kt++) {
        CP_WAIT1();
        __syncthreads();

        if (kt + NSTG - 1 < NKT) {
            int s  = (kt + NSTG - 1) % NSTG;
            int kn = kt + NSTG - 1;
            uint32_t sa = sb + s * STAGE_B;
            #pragma unroll
            for (int i = 0; i < 2; i++) {
                int r = cr + i * 64;
                CP_ASYNC16(sa + (uint32_t)((r * LDK + cc * 8) * 2),
                           Ag + (size_t)r * KC + kn * BKT + cc * 8);
                CP_ASYNC16(sa + TILE_SB + (uint32_t)((r * LDK + cc * 8) * 2),
                           Bg + (size_t)r * KC + kn * BKT + cc * 8);
            }
        }
        CP_COMMIT();

        const uint32_t sA = sb + (kt % NSTG) * STAGE_B;
        const uint32_t sB = sA + TILE_SB;

        #pragma unroll
        for (int kk = 0; kk < 2; kk++) {
            uint32_t afr[4][4];
            uint32_t bfr[4][2];
            #pragma unroll
            for (int mi = 0; mi < 4; mi++) {
                uint32_t addr = sA + (uint32_t)(((wm + mi * 16 + arow) * LDK
                                               + kk * 16 + ahalf) * 2);
                LDMATRIX_X4(afr[mi][0], afr[mi][1], afr[mi][2], afr[mi][3], addr);
            }
            #pragma unroll
            for (int np = 0; np < 2; np++) {
                uint32_t r0, r1, r2, r3;
                uint32_t addr = sB + (uint32_t)(((wn + np * 16 + brow) * LDK
                                               + kk * 16 + bhalf) * 2);
                LDMATRIX_X4(r0, r1, r2, r3, addr);
                bfr[np * 2][0] = r0;  bfr[np * 2][1] = r1;
                bfr[np * 2 + 1][0] = r2;  bfr[np * 2 + 1][1] = r3;
            }
            #pragma unroll
            for (int mi = 0; mi < 4; mi++)
                #pragma unroll
                for (int ni = 0; ni < 4; ni++)
                    MMA16816(acc[mi][ni], afr[mi], bfr[ni]);
        }
    }

    // ---- epilogue ----
    const int g = lane >> 2;
    const int t = lane & 3;
    float* Cb = C + (size_t)(blockIdx.y * 128 + wm) * GN + blockIdx.x * 128 + wn;
    #pragma unroll
    for (int mi = 0; mi < 4; mi++) {
        #pragma unroll
        for (int ni = 0; ni < 4; ni++) {
            float* p = Cb + (size_t)(mi * 16 + g) * GN + ni * 8 + t * 2;
            *(float2*)p              = make_float2(acc[mi][ni][0], acc[mi][ni][1]);
            *(float2*)(p + 8 * GN)   = make_float2(acc[mi][ni][2], acc[mi][ni][3]);
        }
    }
}

// ---------------------------------------------------------------------------
// Sliding-window attention, fp32, online softmax.  (unchanged from R1)
// ---------------------------------------------------------------------------
__global__ __launch_bounds__(128)
void attn_kernel(const float* __restrict__ q, const float* __restrict__ k,
                 const float* __restrict__ v, float* __restrict__ o)
{
    constexpr int BQ = 32;
    __shared__ __align__(16) float Qs[BQ][HDIM];
    __shared__ __align__(16) float Ks[64][HDIM + 4];
    __shared__ __align__(16) float Vs[64][HDIM + 4];

    const int b  = blockIdx.z;
    const int h  = blockIdx.y;
    const int q0 = blockIdx.x * BQ;
    const int tid = threadIdx.x;
    const int r   = tid >> 2;
    const int sub = tid & 3;

    const float* qb = q + (size_t)b * SEQ * DMODEL + h * HDIM;
    const float* kp = k + (size_t)b * SEQ * DMODEL + h * HDIM;
    const float* vp = v + (size_t)b * SEQ * DMODEL + h * HDIM;

    const float scale = 0.125f;

    for (int i = tid; i < BQ * (HDIM/4); i += 128) {
        int row = i >> 4;
        int c4  = (i & 15) * 4;
        float4 t = *(const float4*)(qb + (size_t)(q0 + row) * DMODEL + c4);
        t.x *= scale; t.y *= scale; t.z *= scale; t.w *= scale;
        *(float4*)&Qs[row][c4] = t;
    }
    __syncthreads();

    float4 qr[16];
    #pragma unroll
    for (int i = 0; i < 16; i++) qr[i] = *(const float4*)&Qs[r][i*4];

    const int qidx = q0 + r;
    float m = -INFINITY, l = 0.f;
    float4 oa[16];
    #pragma unroll
    for (int i = 0; i < 16; i++) oa[i] = make_float4(0.f, 0.f, 0.f, 0.f);

    int kstart = max(0, q0 - WIN + 1) & ~63;

    for (int kb = kstart; kb <= q0 + BQ - 1; kb += 64) {
        __syncthreads();
        for (int i = tid; i < 64 * 16; i += 128) {
            int row = i >> 4;
            int c4  = (i & 15) * 4;
            *(float4*)&Ks[row][c4] = *(const float4*)(kp + (size_t)(kb + row) * DMODEL + c4);
            *(float4*)&Vs[row][c4] = *(const float4*)(vp + (size_t)(kb + row) * DMODEL + c4);
        }
        __syncthreads();

        float sc[16];
        float tmax = -INFINITY;
        #pragma unroll
        for (int i = 0; i < 16; i++) {
            int kk = sub + 4 * i;
            int kg = kb + kk;
            float s = -INFINITY;
            if (kg <= qidx && kg >= qidx - WIN + 1) {
                float acc = 0.f;
                #pragma unroll
                for (int d4 = 0; d4 < 16; d4++) {
                    float4 kv = *(const float4*)&Ks[kk][d4*4];
                    acc += qr[d4].x*kv.x + qr[d4].y*kv.y
                         + qr[d4].z*kv.z + qr[d4].w*kv.w;
                }
                s = acc;
            }
            sc[i] = s;
            tmax = fmaxf(tmax, s);
        }
        tmax = fmaxf(tmax, __shfl_xor_sync(0xffffffffu, tmax, 1));
        tmax = fmaxf(tmax, __shfl_xor_sync(0xffffffffu, tmax, 2));

        float mnew = fmaxf(m, tmax);
        float factor = (m == -INFINITY) ? 0.f : __expf(m - mnew);
        l *= factor;
        #pragma unroll
        for (int i = 0; i < 16; i++) {
            oa[i].x *= factor; oa[i].y *= factor;
            oa[i].z *= factor; oa[i].w *= factor;
        }
        #pragma unroll
        for (int i = 0; i < 16; i++) {
            float s = sc[i];
            if (s == -INFINITY) continue;
            float p = __expf(s - mnew);
            l += p;
            int kk = sub + 4 * i;
            #pragma unroll
            for (int d4 = 0; d4 < 16; d4++) {
                float4 vv = *(const float4*)&Vs[kk][d4*4];
                oa[d4].x += p * vv.x; oa[d4].y += p * vv.y;
                oa[d4].z += p * vv.z; oa[d4].w += p * vv.w;
            }
        }
        m = mnew;
    }

    l += __shfl_xor_sync(0xffffffffu, l, 1);
    l += __shfl_xor_sync(0xffffffffu, l, 2);
    #pragma unroll
    for (int i = 0; i < 16; i++) {
        oa[i].x += __shfl_xor_sync(0xffffffffu, oa[i].x, 1);
        oa[i].x += __shfl_xor_sync(0xffffffffu, oa[i].x, 2);
        oa[i].y += __shfl_xor_sync(0xffffffffu, oa[i].y, 1);
        oa[i].y += __shfl_xor_sync(0xffffffffu, oa[i].y, 2);
        oa[i].z += __shfl_xor_sync(0xffffffffu, oa[i].z, 1);
        oa[i].z += __shfl_xor_sync(0xffffffffu, oa[i].z, 2);
        oa[i].w += __shfl_xor_sync(0xffffffffu, oa[i].w, 1);
        oa[i].w += __shfl_xor_sync(0xffffffffu, oa[i].w, 2);
    }

    float inv = 1.f / l;
    float* ob = o + (size_t)(b * SEQ + qidx) * DMODEL + h * HDIM + sub * 16;
    #pragma unroll
    for (int t = 0; t < 4; t++) {
        float4 val = oa[sub * 4 + t];
        val.x *= inv; val.y *= inv; val.z *= inv; val.w *= inv;
        *(float4*)(ob + t * 4) = val;
    }
}

// ---------------------------------------------------------------------------
extern "C" void kernel_launch(void* const* d_in, const int* in_sizes, int n_in,
                              void* d_out, int out_size)
{
    const float* x  = (const float*)d_in[0];
    const float* Wq = (const float*)d_in[1];
    const float* Wk = (const float*)d_in[2];
    const float* Wv = (const float*)d_in[3];
    const float* Wo = (const float*)d_in[4];
    float* out = (float*)d_out;

    float *qp, *kp, *vp, *aop;
    __nv_bfloat16 *xc, *aoc, *wqc, *wkc, *wvc, *woc;
    cudaGetSymbolAddress((void**)&qp,  g_q);
    cudaGetSymbolAddress((void**)&kp,  g_k);
    cudaGetSymbolAddress((void**)&vp,  g_v);
    cudaGetSymbolAddress((void**)&aop, g_ao);
    cudaGetSymbolAddress((void**)&xc,  g_xc);
    cudaGetSymbolAddress((void**)&aoc, g_aoc);
    cudaGetSymbolAddress((void**)&wqc, g_wqc);
    cudaGetSymbolAddress((void**)&wkc, g_wkc);
    cudaGetSymbolAddress((void**)&wvc, g_wvc);
    cudaGetSymbolAddress((void**)&woc, g_woc);

    cudaFuncSetAttribute(gemm_mma, cudaFuncAttributeMaxDynamicSharedMemorySize,
                         SMEM_GEMM);

    // fp32 -> bf16 splits: A-side [hi|hi|lo], B-side [hi|lo|hi]
    conv_A<<<MROWS, 256>>>(x,  xc);
    conv_B<<<DMODEL, 256>>>(Wq, wqc);
    conv_B<<<DMODEL, 256>>>(Wk, wkc);
    conv_B<<<DMODEL, 256>>>(Wv, wvc);
    conv_B<<<DMODEL, 256>>>(Wo, woc);

    dim3 gdim(GN / 128, MROWS / 128);  // (8, 32)
    gemm_mma<<<gdim, 256, SMEM_GEMM>>>(xc, wqc, qp);
    gemm_mma<<<gdim, 256, SMEM_GEMM>>>(xc, wkc, kp);
    gemm_mma<<<gdim, 256, SMEM_GEMM>>>(xc, wvc, vp);

    attn_kernel<<<dim3(SEQ / 32, NHEAD, BATCH), 128>>>(qp, kp, vp, aop);

    conv_A<<<MROWS, 256>>>(aop, aoc);
    gemm_mma<<<gdim, 256, SMEM_GEMM>>>(aoc, woc, out);
}

// round 5
// speedup vs baseline: 4.9792x; 2.1913x over previous
#include <cuda_runtime.h>
#include <cuda_bf16.h>
#include <cstdint>
#include <math.h>

#define BATCH  2
#define SEQ    2048
#define DMODEL 1024
#define NHEAD  16
#define HDIM   64
#define WIN    256
#define MROWS  (BATCH*SEQ)   /* 4096 */

#define KC     3072          /* [hi|hi|lo] x [hi|lo|hi] concatenated K */
#define GN     1024

// ---------------- scratch (allocation-free rule: device globals) ----------------
__device__ float g_q [MROWS*DMODEL];
__device__ float g_k [MROWS*DMODEL];
__device__ float g_v [MROWS*DMODEL];
__device__ float g_ao[MROWS*DMODEL];

__device__ __nv_bfloat16 g_xc [(size_t)MROWS*KC];
__device__ __nv_bfloat16 g_aoc[(size_t)MROWS*KC];
__device__ __nv_bfloat16 g_wqc[(size_t)DMODEL*KC];
__device__ __nv_bfloat16 g_wkc[(size_t)DMODEL*KC];
__device__ __nv_bfloat16 g_wvc[(size_t)DMODEL*KC];
__device__ __nv_bfloat16 g_woc[(size_t)DMODEL*KC];

// =========================================================================
// common helpers
// =========================================================================
__device__ __forceinline__ uint32_t smem_u32(const void* p) {
    uint32_t a;
    asm("{ .reg .u64 t; cvta.to.shared.u64 t, %1; cvt.u32.u64 %0, t; }"
        : "=r"(a) : "l"(p));
    return a;
}

__device__ __forceinline__ void split4(float4 v, uint2& hi, uint2& lo)
{
    __nv_bfloat162 h01 = __floats2bfloat162_rn(v.x, v.y);
    __nv_bfloat162 h23 = __floats2bfloat162_rn(v.z, v.w);
    __nv_bfloat162 l01 = __floats2bfloat162_rn(v.x - __low2float(h01),
                                               v.y - __high2float(h01));
    __nv_bfloat162 l23 = __floats2bfloat162_rn(v.z - __low2float(h23),
                                               v.w - __high2float(h23));
    hi = make_uint2(*(uint32_t*)&h01, *(uint32_t*)&h23);
    lo = make_uint2(*(uint32_t*)&l01, *(uint32_t*)&l23);
}

#define CP_ASYNC16(dst, src) \
    asm volatile("cp.async.cg.shared.global [%0], [%1], 16;" \
                 :: "r"(dst), "l"(src) : "memory")
#define CP_COMMIT() asm volatile("cp.async.commit_group;" ::: "memory")
#define CP_WAIT1()  asm volatile("cp.async.wait_group 1;"  ::: "memory")

#define LDMATRIX_X4(r0, r1, r2, r3, addr) \
    asm volatile("ldmatrix.sync.aligned.m8n8.x4.shared.b16 {%0,%1,%2,%3}, [%4];" \
                 : "=r"(r0), "=r"(r1), "=r"(r2), "=r"(r3) : "r"(addr))

#define LDMATRIX_X4_T(r0, r1, r2, r3, addr) \
    asm volatile("ldmatrix.sync.aligned.m8n8.x4.trans.shared.b16 {%0,%1,%2,%3}, [%4];" \
                 : "=r"(r0), "=r"(r1), "=r"(r2), "=r"(r3) : "r"(addr))

#define MMA16816(d, a, b) \
    asm volatile("mma.sync.aligned.m16n8k16.row.col.f32.bf16.bf16.f32 " \
                 "{%0,%1,%2,%3}, {%4,%5,%6,%7}, {%8,%9}, {%0,%1,%2,%3};" \
                 : "+f"((d)[0]), "+f"((d)[1]), "+f"((d)[2]), "+f"((d)[3]) \
                 : "r"((a)[0]), "r"((a)[1]), "r"((a)[2]), "r"((a)[3]), \
                   "r"((b)[0]), "r"((b)[1]))

// =========================================================================
// fp32 [rows x 1024] -> bf16 [rows x 3072] splits (A: hi|hi|lo; B: hi|lo|hi)
// =========================================================================
__global__ __launch_bounds__(256)
void conv_A(const float* __restrict__ in, __nv_bfloat16* __restrict__ out)
{
    size_t idx = (size_t)blockIdx.x * 256 + threadIdx.x;
    int r  = (int)(idx >> 8);
    int c4 = (int)(idx & 255);
    uint2 hi, lo;
    split4(((const float4*)in)[idx], hi, lo);
    __nv_bfloat16* row = out + (size_t)r * KC;
    *(uint2*)(row + c4 * 4)        = hi;
    *(uint2*)(row + 1024 + c4 * 4) = hi;
    *(uint2*)(row + 2048 + c4 * 4) = lo;
}

__global__ __launch_bounds__(256)
void conv_B(const float* __restrict__ in, __nv_bfloat16* __restrict__ out)
{
    size_t idx = (size_t)blockIdx.x * 256 + threadIdx.x;
    int r  = (int)(idx >> 8);
    int c4 = (int)(idx & 255);
    uint2 hi, lo;
    split4(((const float4*)in)[idx], hi, lo);
    __nv_bfloat16* row = out + (size_t)r * KC;
    *(uint2*)(row + c4 * 4)        = hi;
    *(uint2*)(row + 1024 + c4 * 4) = lo;
    *(uint2*)(row + 2048 + c4 * 4) = hi;
}

// =========================================================================
// C[M,1024] = A[M,3072] * B[1024,3072]^T via mma.sync  (unchanged from R4)
// =========================================================================
#define BKT    32
#define NSTG   3
#define NKT    (KC / BKT)
#define LDK    40
#define TILE_SB (128 * LDK * 2)
#define STAGE_B (2 * TILE_SB)
#define SMEM_GEMM (NSTG * STAGE_B)

__global__ __launch_bounds__(256)
void gemm_mma(const __nv_bfloat16* __restrict__ A,
              const __nv_bfloat16* __restrict__ B,
              float* __restrict__ C)
{
    extern __shared__ __align__(128) char smem[];
    const uint32_t sb = smem_u32(smem);

    const int tid  = threadIdx.x;
    const int lane = tid & 31;
    const int wid  = tid >> 5;
    const int wm   = (wid & 1) * 64;
    const int wn   = (wid >> 1) * 32;

    const __nv_bfloat16* Ag = A + (size_t)(blockIdx.y * 128) * KC;
    const __nv_bfloat16* Bg = B + (size_t)(blockIdx.x * 128) * KC;

    const int cr = tid >> 2;
    const int cc = tid & 3;

    const int arow  = ((lane >> 3) & 1) * 8 + (lane & 7);
    const int ahalf = (lane >> 4) * 8;
    const int brow  = ((lane >> 4) << 3) + (lane & 7);
    const int bhalf = ((lane >> 3) & 1) * 8;

    float acc[4][4][4];
    #pragma unroll
    for (int i = 0; i < 4; i++)
        #pragma unroll
        for (int j = 0; j < 4; j++)
            #pragma unroll
            for (int t = 0; t < 4; t++) acc[i][j][t] = 0.f;

    #pragma unroll
    for (int s = 0; s < NSTG - 1; s++) {
        uint32_t sa = sb + s * STAGE_B;
        #pragma unroll
        for (int i = 0; i < 2; i++) {
            int r = cr + i * 64;
            CP_ASYNC16(sa + (uint32_t)((r * LDK + cc * 8) * 2),
                       Ag + (size_t)r * KC + s * BKT + cc * 8);
            CP_ASYNC16(sa + TILE_SB + (uint32_t)((r * LDK + cc * 8) * 2),
                       Bg + (size_t)r * KC + s * BKT + cc * 8);
        }
        CP_COMMIT();
    }

    for (int kt = 0; kt < NKT; kt++) {
        CP_WAIT1();
        __syncthreads();

        if (kt + NSTG - 1 < NKT) {
            int s  = (kt + NSTG - 1) % NSTG;
            int kn = kt + NSTG - 1;
            uint32_t sa = sb + s * STAGE_B;
            #pragma unroll
            for (int i = 0; i < 2; i++) {
                int r = cr + i * 64;
                CP_ASYNC16(sa + (uint32_t)((r * LDK + cc * 8) * 2),
                           Ag + (size_t)r * KC + kn * BKT + cc * 8);
                CP_ASYNC16(sa + TILE_SB + (uint32_t)((r * LDK + cc * 8) * 2),
                           Bg + (size_t)r * KC + kn * BKT + cc * 8);
            }
        }
        CP_COMMIT();

        const uint32_t sA = sb + (kt % NSTG) * STAGE_B;
        const uint32_t sB = sA + TILE_SB;

        #pragma unroll
        for (int kk = 0; kk < 2; kk++) {
            uint32_t afr[4][4];
            uint32_t bfr[4][2];
            #pragma unroll
            for (int mi = 0; mi < 4; mi++) {
                uint32_t addr = sA + (uint32_t)(((wm + mi * 16 + arow) * LDK
                                               + kk * 16 + ahalf) * 2);
                LDMATRIX_X4(afr[mi][0], afr[mi][1], afr[mi][2], afr[mi][3], addr);
            }
            #pragma unroll
            for (int np = 0; np < 2; np++) {
                uint32_t r0, r1, r2, r3;
                uint32_t addr = sB + (uint32_t)(((wn + np * 16 + brow) * LDK
                                               + kk * 16 + bhalf) * 2);
                LDMATRIX_X4(r0, r1, r2, r3, addr);
                bfr[np * 2][0] = r0;  bfr[np * 2][1] = r1;
                bfr[np * 2 + 1][0] = r2;  bfr[np * 2 + 1][1] = r3;
            }
            #pragma unroll
            for (int mi = 0; mi < 4; mi++)
                #pragma unroll
                for (int ni = 0; ni < 4; ni++)
                    MMA16816(acc[mi][ni], afr[mi], bfr[ni]);
        }
    }

    const int g = lane >> 2;
    const int t = lane & 3;
    float* Cb = C + (size_t)(blockIdx.y * 128 + wm) * GN + blockIdx.x * 128 + wn;
    #pragma unroll
    for (int mi = 0; mi < 4; mi++) {
        #pragma unroll
        for (int ni = 0; ni < 4; ni++) {
            float* p = Cb + (size_t)(mi * 16 + g) * GN + ni * 8 + t * 2;
            *(float2*)p              = make_float2(acc[mi][ni][0], acc[mi][ni][1]);
            *(float2*)(p + 8 * GN)   = make_float2(acc[mi][ni][2], acc[mi][ni][3]);
        }
    }
}

// =========================================================================
// Flash sliding-window attention via mma.sync.
// CTA = 64 queries x one (b,h), 4 warps (16 query rows each).
// smem tiles (bf16, row stride LDA): Q' [64 x (hi64|lo64)], K' same, V' same.
// S = Q'K'^T via split segments (hi*hi + hi*lo + lo*hi), 12 k16 steps.
// PV: P_hi/P_lo repacked from S fragments; V via ldmatrix.trans;
//     segments P_hi*V_hi + P_hi*V_lo + P_lo*V_hi.
// =========================================================================
#define LDA 136                       /* bf16 row stride: 272B, 16B-aligned  */
#define ATTN_SMEM (3 * 64 * LDA * 2)  /* 52224 B */

__global__ __launch_bounds__(128)
void attn_mma(const float* __restrict__ q, const float* __restrict__ k,
              const float* __restrict__ v, float* __restrict__ o)
{
    extern __shared__ __align__(128) char smem[];
    __nv_bfloat16* Qs = (__nv_bfloat16*)smem;
    __nv_bfloat16* Ks = Qs + 64 * LDA;
    __nv_bfloat16* Vs = Ks + 64 * LDA;

    const int b   = blockIdx.z;
    const int h   = blockIdx.y;
    const int q0  = blockIdx.x * 64;
    const int tid = threadIdx.x;
    const int lane = tid & 31;
    const int wid  = tid >> 5;
    const int wm   = wid * 16;            // warp's query-row offset

    const float* qb = q + (size_t)(b * SEQ + q0) * DMODEL + h * HDIM;
    const float* kp = k + (size_t)b * SEQ * DMODEL + h * HDIM;
    const float* vp = v + (size_t)b * SEQ * DMODEL + h * HDIM;

    // ---- load + scale + split Q tile (64x64 fp32 -> [hi|lo] bf16) ----
    #pragma unroll
    for (int j = 0; j < 8; j++) {
        int idx = tid + j * 128;         // 0..1023 float4s
        int row = idx >> 4;
        int c4  = idx & 15;
        float4 t = *(const float4*)(qb + (size_t)row * DMODEL + c4 * 4);
        t.x *= 0.125f; t.y *= 0.125f; t.z *= 0.125f; t.w *= 0.125f;
        uint2 hi, lo;
        split4(t, hi, lo);
        *(uint2*)(Qs + row * LDA + c4 * 4)      = hi;
        *(uint2*)(Qs + row * LDA + 64 + c4 * 4) = lo;
    }
    __syncthreads();

    const int g  = lane >> 2;
    const int t4 = lane & 3;
    const int arow  = ((lane >> 3) & 1) * 8 + (lane & 7);
    const int ahalf = (lane >> 4) * 8;
    const int brow  = ((lane >> 4) << 3) + (lane & 7);
    const int bhalf = ((lane >> 3) & 1) * 8;
    const int vrow  = (lane & 7) + ((lane >> 3) & 1) * 8;   // key within 16
    const int vcol  = (lane >> 4) * 8;                      // dim within 16

    const uint32_t sQ = smem_u32(Qs);
    const uint32_t sK = smem_u32(Ks);
    const uint32_t sV = smem_u32(Vs);

    float m0 = -1e30f, m1 = -1e30f, l0 = 0.f, l1 = 0.f;
    float of[8][4];
    #pragma unroll
    for (int i = 0; i < 8; i++)
        #pragma unroll
        for (int j = 0; j < 4; j++) of[i][j] = 0.f;

    const int qrow0 = q0 + wm + g;
    const int qrow1 = qrow0 + 8;
    const int kstart = max(0, q0 - 256);

    for (int kb = kstart; kb <= q0; kb += 64) {
        __syncthreads();   // previous tile fully consumed
        #pragma unroll
        for (int j = 0; j < 8; j++) {
            int idx = tid + j * 128;
            int row = idx >> 4;
            int c4  = idx & 15;
            uint2 hi, lo;
            float4 tk = *(const float4*)(kp + (size_t)(kb + row) * DMODEL + c4 * 4);
            split4(tk, hi, lo);
            *(uint2*)(Ks + row * LDA + c4 * 4)      = hi;
            *(uint2*)(Ks + row * LDA + 64 + c4 * 4) = lo;
            float4 tv = *(const float4*)(vp + (size_t)(kb + row) * DMODEL + c4 * 4);
            split4(tv, hi, lo);
            *(uint2*)(Vs + row * LDA + c4 * 4)      = hi;
            *(uint2*)(Vs + row * LDA + 64 + c4 * 4) = lo;
        }
        __syncthreads();

        // ---- S = Q' K'^T : 12 k16 steps over segments ----
        float sf[8][4];
        #pragma unroll
        for (int i = 0; i < 8; i++)
            #pragma unroll
            for (int j = 0; j < 4; j++) sf[i][j] = 0.f;

        #pragma unroll
        for (int s = 0; s < 12; s++) {
            int acol = ((s < 8) ? 0 : 64) + (s & 3) * 16;
            int bcol = ((s >= 4 && s < 8) ? 64 : 0) + (s & 3) * 16;
            uint32_t af[4];
            LDMATRIX_X4(af[0], af[1], af[2], af[3],
                        sQ + (uint32_t)(((wm + arow) * LDA + acol + ahalf) * 2));
            #pragma unroll
            for (int np = 0; np < 4; np++) {
                uint32_t r0, r1, r2, r3;
                LDMATRIX_X4(r0, r1, r2, r3,
                            sK + (uint32_t)(((np * 16 + brow) * LDA + bcol + bhalf) * 2));
                uint32_t b01[2] = {r0, r1}, b23[2] = {r2, r3};
                MMA16816(sf[np * 2],     af, b01);
                MMA16816(sf[np * 2 + 1], af, b23);
            }
        }

        // ---- mask + online softmax ----
        float tmax0 = -1e30f, tmax1 = -1e30f;
        #pragma unroll
        for (int nt = 0; nt < 8; nt++) {
            int key0 = kb + nt * 8 + t4 * 2;
            int key1 = key0 + 1;
            if (!(key0 <= qrow0 && key0 >= qrow0 - (WIN - 1))) sf[nt][0] = -1e30f;
            if (!(key1 <= qrow0 && key1 >= qrow0 - (WIN - 1))) sf[nt][1] = -1e30f;
            if (!(key0 <= qrow1 && key0 >= qrow1 - (WIN - 1))) sf[nt][2] = -1e30f;
            if (!(key1 <= qrow1 && key1 >= qrow1 - (WIN - 1))) sf[nt][3] = -1e30f;
            tmax0 = fmaxf(tmax0, fmaxf(sf[nt][0], sf[nt][1]));
            tmax1 = fmaxf(tmax1, fmaxf(sf[nt][2], sf[nt][3]));
        }
        tmax0 = fmaxf(tmax0, __shfl_xor_sync(0xffffffffu, tmax0, 1));
        tmax0 = fmaxf(tmax0, __shfl_xor_sync(0xffffffffu, tmax0, 2));
        tmax1 = fmaxf(tmax1, __shfl_xor_sync(0xffffffffu, tmax1, 1));
        tmax1 = fmaxf(tmax1, __shfl_xor_sync(0xffffffffu, tmax1, 2));

        float mn0 = fmaxf(m0, tmax0);
        float mn1 = fmaxf(m1, tmax1);
        float f0 = __expf(m0 - mn0);
        float f1 = __expf(m1 - mn1);
        l0 *= f0; l1 *= f1;
        #pragma unroll
        for (int nt = 0; nt < 8; nt++) {
            of[nt][0] *= f0; of[nt][1] *= f0;
            of[nt][2] *= f1; of[nt][3] *= f1;
        }

        uint32_t phi[8][2], plo[8][2];
        #pragma unroll
        for (int nt = 0; nt < 8; nt++) {
            float p00 = __expf(sf[nt][0] - mn0);
            float p01 = __expf(sf[nt][1] - mn0);
            float p10 = __expf(sf[nt][2] - mn1);
            float p11 = __expf(sf[nt][3] - mn1);
            l0 += p00 + p01;
            l1 += p10 + p11;
            __nv_bfloat162 h0 = __floats2bfloat162_rn(p00, p01);
            __nv_bfloat162 h1 = __floats2bfloat162_rn(p10, p11);
            __nv_bfloat162 e0 = __floats2bfloat162_rn(p00 - __low2float(h0),
                                                      p01 - __high2float(h0));
            __nv_bfloat162 e1 = __floats2bfloat162_rn(p10 - __low2float(h1),
                                                      p11 - __high2float(h1));
            phi[nt][0] = *(uint32_t*)&h0;  phi[nt][1] = *(uint32_t*)&h1;
            plo[nt][0] = *(uint32_t*)&e0;  plo[nt][1] = *(uint32_t*)&e1;
        }
        m0 = mn0; m1 = mn1;

        // ---- O += P V  (P_hi*V_hi + P_hi*V_lo + P_lo*V_hi) ----
        #pragma unroll
        for (int kj = 0; kj < 4; kj++) {
            uint32_t aPhi[4] = { phi[2*kj][0], phi[2*kj][1],
                                 phi[2*kj+1][0], phi[2*kj+1][1] };
            uint32_t aPlo[4] = { plo[2*kj][0], plo[2*kj][1],
                                 plo[2*kj+1][0], plo[2*kj+1][1] };
            #pragma unroll
            for (int np = 0; np < 4; np++) {
                uint32_t r0, r1, r2, r3;
                // V_hi
                LDMATRIX_X4_T(r0, r1, r2, r3,
                    sV + (uint32_t)(((kj * 16 + vrow) * LDA + np * 16 + vcol) * 2));
                {
                    uint32_t b01[2] = {r0, r1}, b23[2] = {r2, r3};
                    MMA16816(of[np * 2],     aPhi, b01);
                    MMA16816(of[np * 2 + 1], aPhi, b23);
                    MMA16816(of[np * 2],     aPlo, b01);
                    MMA16816(of[np * 2 + 1], aPlo, b23);
                }
                // V_lo
                LDMATRIX_X4_T(r0, r1, r2, r3,
                    sV + (uint32_t)(((kj * 16 + vrow) * LDA + 64 + np * 16 + vcol) * 2));
                {
                    uint32_t b01[2] = {r0, r1}, b23[2] = {r2, r3};
                    MMA16816(of[np * 2],     aPhi, b01);
                    MMA16816(of[np * 2 + 1], aPhi, b23);
                }
            }
        }
    }

    // ---- finalize ----
    l0 += __shfl_xor_sync(0xffffffffu, l0, 1);
    l0 += __shfl_xor_sync(0xffffffffu, l0, 2);
    l1 += __shfl_xor_sync(0xffffffffu, l1, 1);
    l1 += __shfl_xor_sync(0xffffffffu, l1, 2);
    float inv0 = 1.f / l0;
    float inv1 = 1.f / l1;

    float* ob = o + (size_t)(b * SEQ + q0 + wm) * DMODEL + h * HDIM;
    #pragma unroll
    for (int nt = 0; nt < 8; nt++) {
        int col = nt * 8 + t4 * 2;
        *(float2*)(ob + (size_t)g * DMODEL + col) =
            make_float2(of[nt][0] * inv0, of[nt][1] * inv0);
        *(float2*)(ob + (size_t)(g + 8) * DMODEL + col) =
            make_float2(of[nt][2] * inv1, of[nt][3] * inv1);
    }
}

// ---------------------------------------------------------------------------
extern "C" void kernel_launch(void* const* d_in, const int* in_sizes, int n_in,
                              void* d_out, int out_size)
{
    const float* x  = (const float*)d_in[0];
    const float* Wq = (const float*)d_in[1];
    const float* Wk = (const float*)d_in[2];
    const float* Wv = (const float*)d_in[3];
    const float* Wo = (const float*)d_in[4];
    float* out = (float*)d_out;

    float *qp, *kp, *vp, *aop;
    __nv_bfloat16 *xc, *aoc, *wqc, *wkc, *wvc, *woc;
    cudaGetSymbolAddress((void**)&qp,  g_q);
    cudaGetSymbolAddress((void**)&kp,  g_k);
    cudaGetSymbolAddress((void**)&vp,  g_v);
    cudaGetSymbolAddress((void**)&aop, g_ao);
    cudaGetSymbolAddress((void**)&xc,  g_xc);
    cudaGetSymbolAddress((void**)&aoc, g_aoc);
    cudaGetSymbolAddress((void**)&wqc, g_wqc);
    cudaGetSymbolAddress((void**)&wkc, g_wkc);
    cudaGetSymbolAddress((void**)&wvc, g_wvc);
    cudaGetSymbolAddress((void**)&woc, g_woc);

    cudaFuncSetAttribute(gemm_mma, cudaFuncAttributeMaxDynamicSharedMemorySize,
                         SMEM_GEMM);
    cudaFuncSetAttribute(attn_mma, cudaFuncAttributeMaxDynamicSharedMemorySize,
                         ATTN_SMEM);

    conv_A<<<MROWS, 256>>>(x,  xc);
    conv_B<<<DMODEL, 256>>>(Wq, wqc);
    conv_B<<<DMODEL, 256>>>(Wk, wkc);
    conv_B<<<DMODEL, 256>>>(Wv, wvc);
    conv_B<<<DMODEL, 256>>>(Wo, woc);

    dim3 gdim(GN / 128, MROWS / 128);
    gemm_mma<<<gdim, 256, SMEM_GEMM>>>(xc, wqc, qp);
    gemm_mma<<<gdim, 256, SMEM_GEMM>>>(xc, wkc, kp);
    gemm_mma<<<gdim, 256, SMEM_GEMM>>>(xc, wvc, vp);

    attn_mma<<<dim3(SEQ / 64, NHEAD, BATCH), 128, ATTN_SMEM>>>(qp, kp, vp, aop);

    conv_A<<<MROWS, 256>>>(aop, aoc);
    gemm_mma<<<gdim, 256, SMEM_GEMM>>>(aoc, woc, out);
}